// round 9
// baseline (speedup 1.0000x reference)
#include <cuda_runtime.h>
#include <cuda_bf16.h>
#include <cstdint>

#define DIM    1024
#define NHEADS 16
#define HDIM   64
#define BATCH  2
#define SEQ    2048
#define MROWS  4096

// ---------------------------------------------------------------------------
// Global scratch (static; no runtime allocation)
// int8 2-digit operands, packed 4/u32 k-major, with per-row fp32 scales.
// ---------------------------------------------------------------------------
__device__ __align__(128) uint32_t g_x8h [MROWS * 256], g_x8l [MROWS * 256];
__device__ __align__(128) uint32_t g_wq8h[3072 * 256],  g_wq8l[3072 * 256];
__device__ __align__(128) uint32_t g_wp8h[1024 * 256],  g_wp8l[1024 * 256];
__device__ __align__(128) uint32_t g_ao8h[MROWS * 256], g_ao8l[MROWS * 256];
__device__ float g_sx[MROWS], g_swq[3072], g_swp[1024], g_sao[MROWS];
// QKV bf16 hi/lo: [s(3)][bh(32)][seq(2048)][32 u32]  (Q pre-scaled by 0.125)
__device__ __align__(128) uint32_t g_qkvh[3u * 2097152], g_qkvl[3u * 2097152];
// Flash output, plain fp32 [m][1024]
__device__ __align__(128) float g_ao[(size_t)MROWS * DIM];

// ---------------------------------------------------------------------------
// Helpers
// ---------------------------------------------------------------------------
__device__ __forceinline__ uint32_t smem_u32(const void* p) {
    uint32_t a;
    asm("{ .reg .u64 t; cvta.to.shared.u64 t, %1; cvt.u32.u64 %0, t; }" : "=r"(a) : "l"(p));
    return a;
}
__device__ __forceinline__ void ldsm4(uint32_t r[4], uint32_t addr) {
    asm volatile("ldmatrix.sync.aligned.m8n8.x4.shared.b16 {%0,%1,%2,%3}, [%4];"
                 : "=r"(r[0]), "=r"(r[1]), "=r"(r[2]), "=r"(r[3]) : "r"(addr));
}
__device__ __forceinline__ void ldsm4t(uint32_t r[4], uint32_t addr) {
    asm volatile("ldmatrix.sync.aligned.m8n8.x4.trans.shared.b16 {%0,%1,%2,%3}, [%4];"
                 : "=r"(r[0]), "=r"(r[1]), "=r"(r[2]), "=r"(r[3]) : "r"(addr));
}
__device__ __forceinline__ void mma_bf(float c[4], const uint32_t a[4], const uint32_t b[2]) {
    asm volatile(
        "mma.sync.aligned.m16n8k16.row.col.f32.bf16.bf16.f32 "
        "{%0,%1,%2,%3}, {%4,%5,%6,%7}, {%8,%9}, {%0,%1,%2,%3};"
        : "+f"(c[0]), "+f"(c[1]), "+f"(c[2]), "+f"(c[3])
        : "r"(a[0]), "r"(a[1]), "r"(a[2]), "r"(a[3]), "r"(b[0]), "r"(b[1]));
}
__device__ __forceinline__ void mma_s8(int c[4], const uint32_t a[4], const uint32_t b[2]) {
    asm volatile(
        "mma.sync.aligned.m16n8k32.row.col.s32.s8.s8.s32 "
        "{%0,%1,%2,%3}, {%4,%5,%6,%7}, {%8,%9}, {%0,%1,%2,%3};"
        : "+r"(c[0]), "+r"(c[1]), "+r"(c[2]), "+r"(c[3])
        : "r"(a[0]), "r"(a[1]), "r"(a[2]), "r"(a[3]), "r"(b[0]), "r"(b[1]));
}
__device__ __forceinline__ uint32_t packbf(float x, float y) {
    unsigned short ux = __bfloat16_as_ushort(__float2bfloat16(x));
    unsigned short uy = __bfloat16_as_ushort(__float2bfloat16(y));
    return (uint32_t)ux | ((uint32_t)uy << 16);
}
__device__ __forceinline__ void hilo2(float x, float y, uint32_t& hi, uint32_t& lo) {
    float hx = __bfloat162float(__float2bfloat16(x));
    float hy = __bfloat162float(__float2bfloat16(y));
    hi = packbf(x, y);
    lo = packbf(x - hx, y - hy);
}
__device__ __forceinline__ void cpa16(uint32_t dst, const void* src) {
    asm volatile("cp.async.cg.shared.global [%0], [%1], 16;" :: "r"(dst), "l"(src));
}
#define CP_COMMIT() asm volatile("cp.async.commit_group;" ::: "memory")
#define CP_WAIT(n)  asm volatile("cp.async.wait_group %0;" :: "n"(n) : "memory")

// ---------------------------------------------------------------------------
// split8: fp32 [rows][1024] -> int8 2-digit (hi, lo packed 4/u32) + row scale
// One block per row, 256 threads.
// ---------------------------------------------------------------------------
__global__ __launch_bounds__(256)
void split8(const float* __restrict__ in, uint32_t* __restrict__ hi,
            uint32_t* __restrict__ lo, float* __restrict__ scale)
{
    const int row = blockIdx.x, tid = threadIdx.x;
    const int lane = tid & 31, wid = tid >> 5;
    float4 v = ((const float4*)in)[row * 256 + tid];
    float m = fmaxf(fmaxf(fabsf(v.x), fabsf(v.y)), fmaxf(fabsf(v.z), fabsf(v.w)));
    #pragma unroll
    for (int off = 16; off > 0; off >>= 1)
        m = fmaxf(m, __shfl_xor_sync(0xffffffffu, m, off));
    __shared__ float wmax[8];
    if (lane == 0) wmax[wid] = m;
    __syncthreads();
    float rm = wmax[0];
    #pragma unroll
    for (int i = 1; i < 8; i++) rm = fmaxf(rm, wmax[i]);
    rm = fmaxf(rm, 1e-20f);
    const float s = rm * (1.0f / 127.4f);
    if (tid == 0) scale[row] = s;
    const float inv = 127.4f / rm;

    float r0 = v.x * inv, r1 = v.y * inv, r2 = v.z * inv, r3 = v.w * inv;
    int h0 = __float2int_rn(r0), h1 = __float2int_rn(r1);
    int h2 = __float2int_rn(r2), h3 = __float2int_rn(r3);
    int l0 = __float2int_rn((r0 - h0) * 256.f);
    int l1 = __float2int_rn((r1 - h1) * 256.f);
    int l2 = __float2int_rn((r2 - h2) * 256.f);
    int l3 = __float2int_rn((r3 - h3) * 256.f);
    l0 = max(-128, min(127, l0)); l1 = max(-128, min(127, l1));
    l2 = max(-128, min(127, l2)); l3 = max(-128, min(127, l3));
    hi[row * 256 + tid] = (h0 & 0xff) | ((h1 & 0xff) << 8) | ((h2 & 0xff) << 16) | ((h3 & 0xff) << 24);
    lo[row * 256 + tid] = (l0 & 0xff) | ((l1 & 0xff) << 8) | ((l2 & 0xff) << 16) | ((l3 & 0xff) << 24);
}

// ---------------------------------------------------------------------------
// mm3: int8 2-digit GEMM. C[M,N] = A@B^T, 3 IMMA terms (hh; hl+lh @ 1/256).
// Block 128x128, 512 thr (16 warps, 32x32 warp tile), BK=128 (one 128B row
// per stage row!), 3-stage cp.async. smem/stage 64KB: Ah/Al/Bh/Bl 16KB each.
// EPI 0: scatter bf16 hi/lo QKV (Q scaled 0.125). EPI 1: fp32 + bias.
// ---------------------------------------------------------------------------
template <int EPI>
__global__ __launch_bounds__(512)
void mm3(const uint32_t* __restrict__ Ah, const uint32_t* __restrict__ Al,
         const uint32_t* __restrict__ Bh, const uint32_t* __restrict__ Bl,
         const float* __restrict__ sA, const float* __restrict__ sB,
         const float* __restrict__ bias, float* __restrict__ Cout,
         uint32_t* __restrict__ qh, uint32_t* __restrict__ ql,
         int N, int K)
{
    extern __shared__ __align__(128) uint32_t sm[];
    const int tid = threadIdx.x, lane = tid & 31, wid = tid >> 5;
    const int m0 = blockIdx.y * 128, n0 = blockIdx.x * 128;
    const int wm = (wid & 3) * 32, wn = (wid >> 2) * 32;
    const uint32_t base = smem_u32(sm);
    const int T    = K >> 7;   // k128 stages
    const int KU   = K >> 2;   // u32 per row

    const int arow = lane & 15, aco = lane >> 4;
    const int brow = (lane & 7) | ((lane & 16) >> 1), bco = (lane & 8) >> 3;

    auto issue = [&](int t) {
        int st  = t % 3;
        int kc0 = t << 3;                          // 8 16B-chunks per k128
        #pragma unroll
        for (int it = 0; it < 8; it++) {
            int idx = tid + it * 512;              // 0..4095
            int blk = idx >> 10;                   // 0 Ah, 1 Al, 2 Bh, 3 Bl
            int row = (idx >> 3) & 127;
            int ch  = idx & 7;
            const uint32_t* sp = (blk == 0) ? Ah : (blk == 1) ? Al
                               : (blk == 2) ? Bh : Bl;
            int grow = ((blk >> 1) ? n0 : m0) + row;
            const void* src = sp + ((size_t)grow * KU + (kc0 + ch) * 4);
            uint32_t dst = base + st * 65536 + blk * 16384
                         + row * 128 + ((ch ^ (row & 7)) * 16);
            cpa16(dst, src);
        }
    };

    int hh[2][4][4] = {};
    int xx[2][4][4] = {};

    issue(0); CP_COMMIT();
    issue(1); CP_COMMIT();

    for (int t = 0; t < T; t++) {
        if (t + 2 < T) { issue(t + 2); CP_COMMIT(); CP_WAIT(2); }
        else           { CP_WAIT(0); }
        __syncthreads();

        const uint32_t sOff = base + (t % 3) * 65536;
        #pragma unroll
        for (int kk = 0; kk < 4; kk++) {           // k32 steps
            uint32_t aH[2][4], aL[2][4], bH[2][4], bL[2][4];
            #pragma unroll
            for (int mt = 0; mt < 2; mt++) {
                int r = wm + mt * 16 + arow;
                int c = (kk * 2 + aco) ^ (r & 7);
                ldsm4(aH[mt], sOff + r * 128 + c * 16);
                ldsm4(aL[mt], sOff + 16384 + r * 128 + c * 16);
            }
            #pragma unroll
            for (int g = 0; g < 2; g++) {
                int r = wn + g * 16 + brow;
                int c = (kk * 2 + bco) ^ (r & 7);
                ldsm4(bH[g], sOff + 32768 + r * 128 + c * 16);
                ldsm4(bL[g], sOff + 49152 + r * 128 + c * 16);
            }
            // hh
            #pragma unroll
            for (int mt = 0; mt < 2; mt++)
                #pragma unroll
                for (int nt = 0; nt < 4; nt++)
                    mma_s8(hh[mt][nt], aH[mt], &bH[nt >> 1][(nt & 1) * 2]);
            // cross: aH*bL + aL*bH, shared 1/256 scale
            #pragma unroll
            for (int mt = 0; mt < 2; mt++)
                #pragma unroll
                for (int nt = 0; nt < 4; nt++)
                    mma_s8(xx[mt][nt], aH[mt], &bL[nt >> 1][(nt & 1) * 2]);
            #pragma unroll
            for (int mt = 0; mt < 2; mt++)
                #pragma unroll
                for (int nt = 0; nt < 4; nt++)
                    mma_s8(xx[mt][nt], aL[mt], &bH[nt >> 1][(nt & 1) * 2]);
        }
        __syncthreads();
    }

    const int r = lane >> 2, j = (lane & 3) * 2;
    if (EPI == 0) {
        const int sidx = n0 >> 10;
        const float qs = (sidx == 0) ? 0.125f : 1.0f;
        uint32_t* H = qh + (size_t)sidx * 2097152;
        uint32_t* L = ql + (size_t)sidx * 2097152;
        #pragma unroll
        for (int mt = 0; mt < 2; mt++) {
            int mA = m0 + wm + mt * 16 + r;
            float sa0 = sA[mA] * qs, sa1 = sA[mA + 8] * qs;
            int b = mA >> 11, q = mA & 2047;
            #pragma unroll
            for (int nt = 0; nt < 4; nt++) {
                int n = n0 + wn + nt * 8 + j;
                float sb0 = sB[n], sb1 = sB[n + 1];
                float v0 = sa0 * sb0 * ((float)hh[mt][nt][0] + (float)xx[mt][nt][0] * (1.f / 256.f));
                float v1 = sa0 * sb1 * ((float)hh[mt][nt][1] + (float)xx[mt][nt][1] * (1.f / 256.f));
                float v2 = sa1 * sb0 * ((float)hh[mt][nt][2] + (float)xx[mt][nt][2] * (1.f / 256.f));
                float v3 = sa1 * sb1 * ((float)hh[mt][nt][3] + (float)xx[mt][nt][3] * (1.f / 256.f));
                int rin = n & 1023, h = rin >> 6, d = rin & 63;
                size_t o1 = (((size_t)(b * 16 + h)) * 2048 + q) * 32 + (d >> 1);
                uint32_t uh, ulw;
                hilo2(v0, v1, uh, ulw);
                H[o1] = uh; L[o1] = ulw;
                hilo2(v2, v3, uh, ulw);
                H[o1 + 8 * 32] = uh; L[o1 + 8 * 32] = ulw;
            }
        }
    } else {
        #pragma unroll
        for (int mt = 0; mt < 2; mt++) {
            int mA = m0 + wm + mt * 16 + r;
            float sa0 = sA[mA], sa1 = sA[mA + 8];
            #pragma unroll
            for (int nt = 0; nt < 4; nt++) {
                int c = n0 + wn + nt * 8 + j;
                float sb0 = sB[c], sb1 = sB[c + 1];
                float b0 = bias[c], b1 = bias[c + 1];
                float v0 = sa0 * sb0 * ((float)hh[mt][nt][0] + (float)xx[mt][nt][0] * (1.f / 256.f)) + b0;
                float v1 = sa0 * sb1 * ((float)hh[mt][nt][1] + (float)xx[mt][nt][1] * (1.f / 256.f)) + b1;
                float v2 = sa1 * sb0 * ((float)hh[mt][nt][2] + (float)xx[mt][nt][2] * (1.f / 256.f)) + b0;
                float v3 = sa1 * sb1 * ((float)hh[mt][nt][3] + (float)xx[mt][nt][3] * (1.f / 256.f)) + b1;
                *(float2*)(Cout + (size_t)mA * N + c) = make_float2(v0, v1);
                *(float2*)(Cout + (size_t)(mA + 8) * N + c) = make_float2(v2, v3);
            }
        }
    }
}

// ---------------------------------------------------------------------------
// Flash attention, HMMA bf16 hi/lo, cp.async 3-stage 64-key KV ring.
// Block = 256 queries of one (b,h), 512 thr / 16 warps (warp owns 16 rows).
// smem: Qhi 0 (32KB), Qlo 32768; KV stage s at 65536+s*32768. Total 160KB.
// Epilogue writes plain fp32 g_ao.
// ---------------------------------------------------------------------------
__global__ __launch_bounds__(512)
void flash2()
{
    extern __shared__ __align__(128) uint32_t sm[];
    const int tid = threadIdx.x, lane = tid & 31, w = tid >> 5;
    const int bh = blockIdx.y, b = bh >> 4, h = bh & 15;
    const int q0 = blockIdx.x * 256;
    const uint32_t base = smem_u32(sm);

    const int arow = lane & 15, aco = lane >> 4;
    const int brow = (lane & 7) | ((lane & 16) >> 1), bco = (lane & 8) >> 3;

    #pragma unroll
    for (int it = 0; it < 8; it++) {
        int idx = tid + it * 512;
        int lohf = idx >= 2048;
        int row = (idx >> 3) & 255, ch = idx & 7;
        const uint32_t* sp = lohf ? g_qkvl : g_qkvh;
        const void* src = sp + ((size_t)bh * 2048 + q0 + row) * 32 + ch * 4;
        uint32_t dst = base + lohf * 32768 + row * 128 + ((ch ^ (row & 7)) * 16);
        cpa16(dst, src);
    }
    CP_COMMIT();

    auto issueKV = [&](int t) {
        int st = t % 3, s0 = t * 64;
        #pragma unroll
        for (int it = 0; it < 4; it++) {
            int idx = tid + it * 512;
            int tensor = idx >> 10;
            int lohf = (idx >> 9) & 1;
            int row = (idx >> 3) & 63, ch = idx & 7;
            const uint32_t* sp = lohf ? g_qkvl : g_qkvh;
            const void* src = sp + (size_t)(1 + tensor) * 2097152
                            + ((size_t)bh * 2048 + s0 + row) * 32 + ch * 4;
            uint32_t dst = base + 65536 + st * 32768 + tensor * 16384
                         + lohf * 8192 + row * 128 + ((ch ^ (row & 7)) * 16);
            cpa16(dst, src);
        }
    };

    issueKV(0); CP_COMMIT();

    float m_a = -1e30f, m_b = -1e30f, l_a = 0.f, l_b = 0.f;
    float o[8][4] = {};

    const int NT = SEQ / 64;
    for (int t = 0; t < NT; t++) {
        if (t + 1 < NT) { issueKV(t + 1); CP_COMMIT(); CP_WAIT(1); }
        else            { CP_WAIT(0); }
        __syncthreads();

        const uint32_t kBase = base + 65536 + (t % 3) * 32768;
        const uint32_t vBase = kBase + 16384;

        float s[8][4] = {};
        #pragma unroll
        for (int kk = 0; kk < 4; kk++) {
            uint32_t aH[4], aL[4];
            {
                int r = w * 16 + arow;
                int c = (kk * 2 + aco) ^ (r & 7);
                ldsm4(aH, base + r * 128 + c * 16);
                ldsm4(aL, base + 32768 + r * 128 + c * 16);
            }
            #pragma unroll
            for (int g = 0; g < 4; g++) {
                int rb = g * 16 + brow;
                int cb = (kk * 2 + bco) ^ (rb & 7);
                uint32_t bHf[4];
                ldsm4(bHf, kBase + rb * 128 + cb * 16);
                mma_bf(s[2 * g],     aH, &bHf[0]);
                mma_bf(s[2 * g + 1], aH, &bHf[2]);
            }
            #pragma unroll
            for (int g = 0; g < 4; g++) {
                int rb = g * 16 + brow;
                int cb = (kk * 2 + bco) ^ (rb & 7);
                uint32_t bLf[4];
                ldsm4(bLf, kBase + 8192 + rb * 128 + cb * 16);
                mma_bf(s[2 * g],     aH, &bLf[0]);
                mma_bf(s[2 * g + 1], aH, &bLf[2]);
            }
            #pragma unroll
            for (int g = 0; g < 4; g++) {
                int rb = g * 16 + brow;
                int cb = (kk * 2 + bco) ^ (rb & 7);
                uint32_t bHf[4];
                ldsm4(bHf, kBase + rb * 128 + cb * 16);
                mma_bf(s[2 * g],     aL, &bHf[0]);
                mma_bf(s[2 * g + 1], aL, &bHf[2]);
            }
        }

        float mxa = -1e30f, mxb = -1e30f;
        #pragma unroll
        for (int nt = 0; nt < 8; nt++) {
            mxa = fmaxf(mxa, fmaxf(s[nt][0], s[nt][1]));
            mxb = fmaxf(mxb, fmaxf(s[nt][2], s[nt][3]));
        }
        mxa = fmaxf(mxa, __shfl_xor_sync(0xffffffffu, mxa, 1));
        mxa = fmaxf(mxa, __shfl_xor_sync(0xffffffffu, mxa, 2));
        mxb = fmaxf(mxb, __shfl_xor_sync(0xffffffffu, mxb, 1));
        mxb = fmaxf(mxb, __shfl_xor_sync(0xffffffffu, mxb, 2));
        float mna = fmaxf(m_a, mxa), mnb = fmaxf(m_b, mxb);
        float alA = __expf(m_a - mna), alB = __expf(m_b - mnb);
        m_a = mna; m_b = mnb;
        float suma = 0.f, sumb = 0.f;
        #pragma unroll
        for (int nt = 0; nt < 8; nt++) {
            s[nt][0] = __expf(s[nt][0] - mna); suma += s[nt][0];
            s[nt][1] = __expf(s[nt][1] - mna); suma += s[nt][1];
            s[nt][2] = __expf(s[nt][2] - mnb); sumb += s[nt][2];
            s[nt][3] = __expf(s[nt][3] - mnb); sumb += s[nt][3];
        }
        suma += __shfl_xor_sync(0xffffffffu, suma, 1);
        suma += __shfl_xor_sync(0xffffffffu, suma, 2);
        sumb += __shfl_xor_sync(0xffffffffu, sumb, 1);
        sumb += __shfl_xor_sync(0xffffffffu, sumb, 2);
        l_a = l_a * alA + suma;
        l_b = l_b * alB + sumb;
        #pragma unroll
        for (int dt = 0; dt < 8; dt++) {
            o[dt][0] *= alA; o[dt][1] *= alA;
            o[dt][2] *= alB; o[dt][3] *= alB;
        }

        #pragma unroll
        for (int kc = 0; kc < 4; kc++) {
            uint32_t pH[4], pL[4];
            hilo2(s[2 * kc][0],     s[2 * kc][1],     pH[0], pL[0]);
            hilo2(s[2 * kc][2],     s[2 * kc][3],     pH[1], pL[1]);
            hilo2(s[2 * kc + 1][0], s[2 * kc + 1][1], pH[2], pL[2]);
            hilo2(s[2 * kc + 1][2], s[2 * kc + 1][3], pH[3], pL[3]);
            int rv = kc * 16 + arow;
            #pragma unroll
            for (int g = 0; g < 4; g++) {
                int cv = (g * 2 + aco) ^ (rv & 7);
                uint32_t vHf[4];
                ldsm4t(vHf, vBase + rv * 128 + cv * 16);
                mma_bf(o[2 * g],     pH, &vHf[0]);
                mma_bf(o[2 * g + 1], pH, &vHf[2]);
            }
            #pragma unroll
            for (int g = 0; g < 4; g++) {
                int cv = (g * 2 + aco) ^ (rv & 7);
                uint32_t vLf[4];
                ldsm4t(vLf, vBase + 8192 + rv * 128 + cv * 16);
                mma_bf(o[2 * g],     pH, &vLf[0]);
                mma_bf(o[2 * g + 1], pH, &vLf[2]);
            }
            #pragma unroll
            for (int g = 0; g < 4; g++) {
                int cv = (g * 2 + aco) ^ (rv & 7);
                uint32_t vHf[4];
                ldsm4t(vHf, vBase + rv * 128 + cv * 16);
                mma_bf(o[2 * g],     pL, &vHf[0]);
                mma_bf(o[2 * g + 1], pL, &vHf[2]);
            }
        }
    }

    // Epilogue: normalize, write fp32 rows to g_ao [m][1024]
    float ia = 1.f / l_a, ib = 1.f / l_b;
    size_t mA = (size_t)b * SEQ + q0 + w * 16 + (lane >> 2);
    float* Oa = g_ao + mA * DIM + h * 64;
    float* Ob = Oa + 8 * DIM;
    #pragma unroll
    for (int dt = 0; dt < 8; dt++) {
        int c = dt * 8 + (lane & 3) * 2;
        *(float2*)(Oa + c) = make_float2(o[dt][0] * ia, o[dt][1] * ia);
        *(float2*)(Ob + c) = make_float2(o[dt][2] * ib, o[dt][3] * ib);
    }
}

// ---------------------------------------------------------------------------
extern "C" void kernel_launch(void* const* d_in, const int* in_sizes, int n_in,
                              void* d_out, int out_size)
{
    const float* x      = (const float*)d_in[0];
    const float* w_qkv  = (const float*)d_in[1];
    const float* w_proj = (const float*)d_in[2];
    const float* b_proj = (const float*)d_in[3];
    float* out = (float*)d_out;

    void *px8h, *px8l, *pwq8h, *pwq8l, *pwp8h, *pwp8l, *pao8h, *pao8l;
    void *psx, *pswq, *pswp, *psao, *pqh, *pql, *pao;
    cudaGetSymbolAddress(&px8h, g_x8h);   cudaGetSymbolAddress(&px8l, g_x8l);
    cudaGetSymbolAddress(&pwq8h, g_wq8h); cudaGetSymbolAddress(&pwq8l, g_wq8l);
    cudaGetSymbolAddress(&pwp8h, g_wp8h); cudaGetSymbolAddress(&pwp8l, g_wp8l);
    cudaGetSymbolAddress(&pao8h, g_ao8h); cudaGetSymbolAddress(&pao8l, g_ao8l);
    cudaGetSymbolAddress(&psx, g_sx);     cudaGetSymbolAddress(&pswq, g_swq);
    cudaGetSymbolAddress(&pswp, g_swp);   cudaGetSymbolAddress(&psao, g_sao);
    cudaGetSymbolAddress(&pqh, g_qkvh);   cudaGetSymbolAddress(&pql, g_qkvl);
    cudaGetSymbolAddress(&pao, g_ao);

    cudaFuncSetAttribute(mm3<0>, cudaFuncAttributeMaxDynamicSharedMemorySize, 196608);
    cudaFuncSetAttribute(mm3<1>, cudaFuncAttributeMaxDynamicSharedMemorySize, 196608);
    cudaFuncSetAttribute(flash2, cudaFuncAttributeMaxDynamicSharedMemorySize, 163840);

    // 1) Quantize inputs to 2-digit int8
    split8<<<MROWS, 256>>>(x,      (uint32_t*)px8h,  (uint32_t*)px8l,  (float*)psx);
    split8<<<3072, 256>>>(w_qkv,  (uint32_t*)pwq8h, (uint32_t*)pwq8l, (float*)pswq);
    split8<<<1024, 256>>>(w_proj, (uint32_t*)pwp8h, (uint32_t*)pwp8l, (float*)pswp);

    // 2) QKV projection (int8 IMMA) -> bf16 hi/lo Q/K/V (Q scaled)
    mm3<0><<<dim3(24, 32), 512, 196608>>>(
        (uint32_t*)px8h, (uint32_t*)px8l, (uint32_t*)pwq8h, (uint32_t*)pwq8l,
        (float*)psx, (float*)pswq, nullptr, nullptr,
        (uint32_t*)pqh, (uint32_t*)pql, 3072, 1024);

    // 3) Attention (bf16 HMMA) -> fp32 AO
    flash2<<<dim3(8, 32), 512, 163840>>>();

    // 4) Quantize AO, then output projection (int8 IMMA) + bias
    split8<<<MROWS, 256>>>((const float*)pao, (uint32_t*)pao8h, (uint32_t*)pao8l, (float*)psao);
    mm3<1><<<dim3(8, 32), 512, 196608>>>(
        (uint32_t*)pao8h, (uint32_t*)pao8l, (uint32_t*)pwp8h, (uint32_t*)pwp8l,
        (float*)psao, (float*)pswp, b_proj, out,
        nullptr, nullptr, 1024, 1024);
}

// round 10
// speedup vs baseline: 3.4019x; 3.4019x over previous
#include <cuda_runtime.h>
#include <cuda_bf16.h>
#include <cuda_fp16.h>
#include <cstdint>

#define DIM    1024
#define NHEADS 16
#define HDIM   64
#define BATCH  2
#define SEQ    2048
#define MROWS  4096

// ---------------------------------------------------------------------------
// Global scratch (static; no runtime allocation)
// A-side operands: fp16 2-digit (hi/lo packed 2/u32, k-major).
// B-side operands (weights): fp16 single digit.
// QKV for flash: bf16 hi/lo (unchanged interface), Q pre-scaled by 0.125.
// ---------------------------------------------------------------------------
__device__ __align__(128) uint32_t g_xh [MROWS * 512], g_xl [MROWS * 512];
__device__ __align__(128) uint32_t g_wqh[3072 * 512];
__device__ __align__(128) uint32_t g_wph[1024 * 512];
__device__ __align__(128) uint32_t g_aoh[MROWS * 512], g_aol[MROWS * 512];
// QKV bf16 hi/lo: [s(3)][bh(32)][seq(2048)][32 u32]
__device__ __align__(128) uint32_t g_qkvh[3u * 2097152], g_qkvl[3u * 2097152];

// ---------------------------------------------------------------------------
// Helpers
// ---------------------------------------------------------------------------
__device__ __forceinline__ uint32_t smem_u32(const void* p) {
    uint32_t a;
    asm("{ .reg .u64 t; cvta.to.shared.u64 t, %1; cvt.u32.u64 %0, t; }" : "=r"(a) : "l"(p));
    return a;
}
__device__ __forceinline__ void ldsm4(uint32_t r[4], uint32_t addr) {
    asm volatile("ldmatrix.sync.aligned.m8n8.x4.shared.b16 {%0,%1,%2,%3}, [%4];"
                 : "=r"(r[0]), "=r"(r[1]), "=r"(r[2]), "=r"(r[3]) : "r"(addr));
}
__device__ __forceinline__ void ldsm4t(uint32_t r[4], uint32_t addr) {
    asm volatile("ldmatrix.sync.aligned.m8n8.x4.trans.shared.b16 {%0,%1,%2,%3}, [%4];"
                 : "=r"(r[0]), "=r"(r[1]), "=r"(r[2]), "=r"(r[3]) : "r"(addr));
}
__device__ __forceinline__ void mma_bf(float c[4], const uint32_t a[4], const uint32_t b[2]) {
    asm volatile(
        "mma.sync.aligned.m16n8k16.row.col.f32.bf16.bf16.f32 "
        "{%0,%1,%2,%3}, {%4,%5,%6,%7}, {%8,%9}, {%0,%1,%2,%3};"
        : "+f"(c[0]), "+f"(c[1]), "+f"(c[2]), "+f"(c[3])
        : "r"(a[0]), "r"(a[1]), "r"(a[2]), "r"(a[3]), "r"(b[0]), "r"(b[1]));
}
__device__ __forceinline__ void mma_h(float c[4], const uint32_t a[4], const uint32_t b[2]) {
    asm volatile(
        "mma.sync.aligned.m16n8k16.row.col.f32.f16.f16.f32 "
        "{%0,%1,%2,%3}, {%4,%5,%6,%7}, {%8,%9}, {%0,%1,%2,%3};"
        : "+f"(c[0]), "+f"(c[1]), "+f"(c[2]), "+f"(c[3])
        : "r"(a[0]), "r"(a[1]), "r"(a[2]), "r"(a[3]), "r"(b[0]), "r"(b[1]));
}
__device__ __forceinline__ uint32_t packbf(float x, float y) {
    unsigned short ux = __bfloat16_as_ushort(__float2bfloat16(x));
    unsigned short uy = __bfloat16_as_ushort(__float2bfloat16(y));
    return (uint32_t)ux | ((uint32_t)uy << 16);
}
__device__ __forceinline__ void hilo2(float x, float y, uint32_t& hi, uint32_t& lo) {
    float hx = __bfloat162float(__float2bfloat16(x));
    float hy = __bfloat162float(__float2bfloat16(y));
    hi = packbf(x, y);
    lo = packbf(x - hx, y - hy);
}
__device__ __forceinline__ uint32_t packh(float x, float y) {
    __half hx = __float2half_rn(x), hy = __float2half_rn(y);
    return (uint32_t)__half_as_ushort(hx) | ((uint32_t)__half_as_ushort(hy) << 16);
}
__device__ __forceinline__ void hilo2h(float x, float y, uint32_t& hi, uint32_t& lo) {
    __half hx = __float2half_rn(x), hy = __float2half_rn(y);
    hi = packh(x, y);
    lo = packh(x - __half2float(hx), y - __half2float(hy));
}
__device__ __forceinline__ void cpa16(uint32_t dst, const void* src) {
    asm volatile("cp.async.cg.shared.global [%0], [%1], 16;" :: "r"(dst), "l"(src));
}
#define CP_COMMIT() asm volatile("cp.async.commit_group;" ::: "memory")
#define CP_WAIT(n)  asm volatile("cp.async.wait_group %0;" :: "n"(n) : "memory")

// ---------------------------------------------------------------------------
// split2h: fp32 [rows][1024] -> fp16 hi/lo packed u32 [rows][512]
// round1h: fp32 -> single fp16 digit
// ---------------------------------------------------------------------------
__global__ __launch_bounds__(256)
void split2h(const float* __restrict__ in, uint32_t* __restrict__ hi,
             uint32_t* __restrict__ lo, int n4)
{
    int g = blockIdx.x * 256 + threadIdx.x;
    if (g >= n4) return;
    float4 v = ((const float4*)in)[g];
    uint32_t h0, l0, h1, l1;
    hilo2h(v.x, v.y, h0, l0);
    hilo2h(v.z, v.w, h1, l1);
    ((uint2*)hi)[g] = make_uint2(h0, h1);
    ((uint2*)lo)[g] = make_uint2(l0, l1);
}
__global__ __launch_bounds__(256)
void round1h(const float* __restrict__ in, uint32_t* __restrict__ hi, int n4)
{
    int g = blockIdx.x * 256 + threadIdx.x;
    if (g >= n4) return;
    float4 v = ((const float4*)in)[g];
    ((uint2*)hi)[g] = make_uint2(packh(v.x, v.y), packh(v.z, v.w));
}

// ---------------------------------------------------------------------------
// GEMM: C[M,N] = A[M,K] @ B[N,K]^T.  A = fp16 2-digit, B = fp16 1-digit.
// 2 MMA terms (HH, LH) -> exact (a)·bH in fp32 accum.
// Block 128x128, 512 thr (16 warps, 32x32 warp tile), BK=64, 3-stage cp.async.
// smem/stage 48KB: Ahi +0, Alo +16K, Bhi +32K.
// EPI 0: scatter bf16 hi/lo QKV (Q scaled 0.125). EPI 1: fp32 + bias.
// ---------------------------------------------------------------------------
template <int EPI>
__global__ __launch_bounds__(512)
void mm2(const uint32_t* __restrict__ Ah, const uint32_t* __restrict__ Al,
         const uint32_t* __restrict__ Bh,
         const float* __restrict__ bias, float* __restrict__ Cout,
         uint32_t* __restrict__ qh, uint32_t* __restrict__ ql,
         int N, int K)
{
    extern __shared__ __align__(128) uint32_t sm[];
    const int tid = threadIdx.x, lane = tid & 31, wid = tid >> 5;
    const int m0 = blockIdx.y * 128, n0 = blockIdx.x * 128;
    const int wm = (wid & 3) * 32, wn = (wid >> 2) * 32;
    const uint32_t base = smem_u32(sm);
    const int T  = K >> 6;   // k64 steps
    const int KC = K >> 3;   // 16B chunks per row

    const int arow = lane & 15, aco = lane >> 4;
    const int brow = (lane & 7) | ((lane & 16) >> 1), bco = (lane & 8) >> 3;

    auto issue = [&](int t) {
        int st  = t % 3;
        int kc0 = t << 3;                          // 8 chunks per k64
        #pragma unroll
        for (int it = 0; it < 6; it++) {
            int idx = tid + it * 512;              // 0..3071
            int blk = idx >> 10;                   // 0 Ahi, 1 Alo, 2 Bhi
            int row = (idx >> 3) & 127;
            int ch  = idx & 7;
            const uint32_t* sp = (blk == 0) ? Ah : (blk == 1) ? Al : Bh;
            int grow = ((blk == 2) ? n0 : m0) + row;
            const void* src = sp + ((size_t)grow * KC + kc0 + ch) * 4;
            uint32_t dst = base + st * 49152 + blk * 16384
                         + row * 128 + ((ch ^ (row & 7)) * 16);
            cpa16(dst, src);
        }
    };

    float acc[2][4][4] = {};

    issue(0); CP_COMMIT();
    issue(1); CP_COMMIT();

    for (int t = 0; t < T; t++) {
        if (t + 2 < T) { issue(t + 2); CP_COMMIT(); CP_WAIT(2); }
        else           { CP_WAIT(0); }
        __syncthreads();

        const uint32_t sOff = base + (t % 3) * 49152;
        #pragma unroll
        for (int kk = 0; kk < 4; kk++) {
            uint32_t aH[2][4], aL[2][4], bH[2][4];
            #pragma unroll
            for (int mt = 0; mt < 2; mt++) {
                int r = wm + mt * 16 + arow;
                int c = (kk * 2 + aco) ^ (r & 7);
                ldsm4(aH[mt], sOff + r * 128 + c * 16);
                ldsm4(aL[mt], sOff + 16384 + r * 128 + c * 16);
            }
            #pragma unroll
            for (int g = 0; g < 2; g++) {
                int r = wn + g * 16 + brow;
                int c = (kk * 2 + bco) ^ (r & 7);
                ldsm4(bH[g], sOff + 32768 + r * 128 + c * 16);
            }
            // Pass 1: aH x bH  (8 independent accumulators)
            #pragma unroll
            for (int mt = 0; mt < 2; mt++)
                #pragma unroll
                for (int nt = 0; nt < 4; nt++)
                    mma_h(acc[mt][nt], aH[mt], &bH[nt >> 1][(nt & 1) * 2]);
            // Pass 2: aL x bH
            #pragma unroll
            for (int mt = 0; mt < 2; mt++)
                #pragma unroll
                for (int nt = 0; nt < 4; nt++)
                    mma_h(acc[mt][nt], aL[mt], &bH[nt >> 1][(nt & 1) * 2]);
        }
        __syncthreads();
    }

    const int r = lane >> 2, j = (lane & 3) * 2;
    if (EPI == 0) {
        const int sidx = n0 >> 10;
        const float qs = (sidx == 0) ? 0.125f : 1.0f;
        uint32_t* H = qh + (size_t)sidx * 2097152;
        uint32_t* L = ql + (size_t)sidx * 2097152;
        #pragma unroll
        for (int mt = 0; mt < 2; mt++) {
            int mA = m0 + wm + mt * 16 + r;
            int b  = mA >> 11, q = mA & 2047;
            #pragma unroll
            for (int nt = 0; nt < 4; nt++) {
                int n = n0 + wn + nt * 8 + j;
                int rin = n & 1023, h = rin >> 6, d = rin & 63;
                size_t o1 = (((size_t)(b * 16 + h)) * 2048 + q) * 32 + (d >> 1);
                uint32_t hh, ll;
                hilo2(acc[mt][nt][0] * qs, acc[mt][nt][1] * qs, hh, ll);
                H[o1] = hh; L[o1] = ll;
                hilo2(acc[mt][nt][2] * qs, acc[mt][nt][3] * qs, hh, ll);
                H[o1 + 8 * 32] = hh; L[o1 + 8 * 32] = ll;
            }
        }
    } else {
        #pragma unroll
        for (int mt = 0; mt < 2; mt++) {
            int mA = m0 + wm + mt * 16 + r;
            #pragma unroll
            for (int nt = 0; nt < 4; nt++) {
                int c = n0 + wn + nt * 8 + j;
                float b0 = bias[c], b1 = bias[c + 1];
                *(float2*)(Cout + (size_t)mA * N + c) =
                    make_float2(acc[mt][nt][0] + b0, acc[mt][nt][1] + b1);
                *(float2*)(Cout + (size_t)(mA + 8) * N + c) =
                    make_float2(acc[mt][nt][2] + b0, acc[mt][nt][3] + b1);
            }
        }
    }
}

// ---------------------------------------------------------------------------
// Flash attention, HMMA bf16 hi/lo (3-term), cp.async 3-stage 64-key KV ring.
// Block = 256 queries of one (b,h), 512 thr / 16 warps (warp owns 16 rows).
// smem: Qhi 0 (32KB), Qlo 32768; KV stage s at 65536+s*32768. Total 160KB.
// Epilogue writes fp16 hi/lo AO for the proj GEMM.
// ---------------------------------------------------------------------------
__global__ __launch_bounds__(512)
void flash2()
{
    extern __shared__ __align__(128) uint32_t sm[];
    const int tid = threadIdx.x, lane = tid & 31, w = tid >> 5;
    const int bh = blockIdx.y, b = bh >> 4, h = bh & 15;
    const int q0 = blockIdx.x * 256;
    const uint32_t base = smem_u32(sm);

    const int arow = lane & 15, aco = lane >> 4;
    const int brow = (lane & 7) | ((lane & 16) >> 1), bco = (lane & 8) >> 3;

    #pragma unroll
    for (int it = 0; it < 8; it++) {
        int idx = tid + it * 512;
        int lohf = idx >= 2048;
        int row = (idx >> 3) & 255, ch = idx & 7;
        const uint32_t* sp = lohf ? g_qkvl : g_qkvh;
        const void* src = sp + ((size_t)bh * 2048 + q0 + row) * 32 + ch * 4;
        uint32_t dst = base + lohf * 32768 + row * 128 + ((ch ^ (row & 7)) * 16);
        cpa16(dst, src);
    }
    CP_COMMIT();

    auto issueKV = [&](int t) {
        int st = t % 3, s0 = t * 64;
        #pragma unroll
        for (int it = 0; it < 4; it++) {
            int idx = tid + it * 512;
            int tensor = idx >> 10;
            int lohf = (idx >> 9) & 1;
            int row = (idx >> 3) & 63, ch = idx & 7;
            const uint32_t* sp = lohf ? g_qkvl : g_qkvh;
            const void* src = sp + (size_t)(1 + tensor) * 2097152
                            + ((size_t)bh * 2048 + s0 + row) * 32 + ch * 4;
            uint32_t dst = base + 65536 + st * 32768 + tensor * 16384
                         + lohf * 8192 + row * 128 + ((ch ^ (row & 7)) * 16);
            cpa16(dst, src);
        }
    };

    issueKV(0); CP_COMMIT();

    float m_a = -1e30f, m_b = -1e30f, l_a = 0.f, l_b = 0.f;
    float o[8][4] = {};

    const int NT = SEQ / 64;
    for (int t = 0; t < NT; t++) {
        if (t + 1 < NT) { issueKV(t + 1); CP_COMMIT(); CP_WAIT(1); }
        else            { CP_WAIT(0); }
        __syncthreads();

        const uint32_t kBase = base + 65536 + (t % 3) * 32768;
        const uint32_t vBase = kBase + 16384;

        float s[8][4] = {};
        #pragma unroll
        for (int kk = 0; kk < 4; kk++) {
            uint32_t aH[4], aL[4];
            {
                int r = w * 16 + arow;
                int c = (kk * 2 + aco) ^ (r & 7);
                ldsm4(aH, base + r * 128 + c * 16);
                ldsm4(aL, base + 32768 + r * 128 + c * 16);
            }
            #pragma unroll
            for (int g = 0; g < 4; g++) {
                int rb = g * 16 + brow;
                int cb = (kk * 2 + bco) ^ (rb & 7);
                uint32_t bHf[4];
                ldsm4(bHf, kBase + rb * 128 + cb * 16);
                mma_bf(s[2 * g],     aH, &bHf[0]);
                mma_bf(s[2 * g + 1], aH, &bHf[2]);
            }
            #pragma unroll
            for (int g = 0; g < 4; g++) {
                int rb = g * 16 + brow;
                int cb = (kk * 2 + bco) ^ (rb & 7);
                uint32_t bLf[4];
                ldsm4(bLf, kBase + 8192 + rb * 128 + cb * 16);
                mma_bf(s[2 * g],     aH, &bLf[0]);
                mma_bf(s[2 * g + 1], aH, &bLf[2]);
            }
            #pragma unroll
            for (int g = 0; g < 4; g++) {
                int rb = g * 16 + brow;
                int cb = (kk * 2 + bco) ^ (rb & 7);
                uint32_t bHf[4];
                ldsm4(bHf, kBase + rb * 128 + cb * 16);
                mma_bf(s[2 * g],     aL, &bHf[0]);
                mma_bf(s[2 * g + 1], aL, &bHf[2]);
            }
        }

        float mxa = -1e30f, mxb = -1e30f;
        #pragma unroll
        for (int nt = 0; nt < 8; nt++) {
            mxa = fmaxf(mxa, fmaxf(s[nt][0], s[nt][1]));
            mxb = fmaxf(mxb, fmaxf(s[nt][2], s[nt][3]));
        }
        mxa = fmaxf(mxa, __shfl_xor_sync(0xffffffffu, mxa, 1));
        mxa = fmaxf(mxa, __shfl_xor_sync(0xffffffffu, mxa, 2));
        mxb = fmaxf(mxb, __shfl_xor_sync(0xffffffffu, mxb, 1));
        mxb = fmaxf(mxb, __shfl_xor_sync(0xffffffffu, mxb, 2));
        float mna = fmaxf(m_a, mxa), mnb = fmaxf(m_b, mxb);
        float alA = __expf(m_a - mna), alB = __expf(m_b - mnb);
        m_a = mna; m_b = mnb;
        float suma = 0.f, sumb = 0.f;
        #pragma unroll
        for (int nt = 0; nt < 8; nt++) {
            s[nt][0] = __expf(s[nt][0] - mna); suma += s[nt][0];
            s[nt][1] = __expf(s[nt][1] - mna); suma += s[nt][1];
            s[nt][2] = __expf(s[nt][2] - mnb); sumb += s[nt][2];
            s[nt][3] = __expf(s[nt][3] - mnb); sumb += s[nt][3];
        }
        suma += __shfl_xor_sync(0xffffffffu, suma, 1);
        suma += __shfl_xor_sync(0xffffffffu, suma, 2);
        sumb += __shfl_xor_sync(0xffffffffu, sumb, 1);
        sumb += __shfl_xor_sync(0xffffffffu, sumb, 2);
        l_a = l_a * alA + suma;
        l_b = l_b * alB + sumb;
        #pragma unroll
        for (int dt = 0; dt < 8; dt++) {
            o[dt][0] *= alA; o[dt][1] *= alA;
            o[dt][2] *= alB; o[dt][3] *= alB;
        }

        #pragma unroll
        for (int kc = 0; kc < 4; kc++) {
            uint32_t pH[4], pL[4];
            hilo2(s[2 * kc][0],     s[2 * kc][1],     pH[0], pL[0]);
            hilo2(s[2 * kc][2],     s[2 * kc][3],     pH[1], pL[1]);
            hilo2(s[2 * kc + 1][0], s[2 * kc + 1][1], pH[2], pL[2]);
            hilo2(s[2 * kc + 1][2], s[2 * kc + 1][3], pH[3], pL[3]);
            int rv = kc * 16 + arow;
            #pragma unroll
            for (int g = 0; g < 4; g++) {
                int cv = (g * 2 + aco) ^ (rv & 7);
                uint32_t vHf[4];
                ldsm4t(vHf, vBase + rv * 128 + cv * 16);
                mma_bf(o[2 * g],     pH, &vHf[0]);
                mma_bf(o[2 * g + 1], pH, &vHf[2]);
            }
            #pragma unroll
            for (int g = 0; g < 4; g++) {
                int cv = (g * 2 + aco) ^ (rv & 7);
                uint32_t vLf[4];
                ldsm4t(vLf, vBase + 8192 + rv * 128 + cv * 16);
                mma_bf(o[2 * g],     pH, &vLf[0]);
                mma_bf(o[2 * g + 1], pH, &vLf[2]);
            }
            #pragma unroll
            for (int g = 0; g < 4; g++) {
                int cv = (g * 2 + aco) ^ (rv & 7);
                uint32_t vHf[4];
                ldsm4t(vHf, vBase + rv * 128 + cv * 16);
                mma_bf(o[2 * g],     pL, &vHf[0]);
                mma_bf(o[2 * g + 1], pL, &vHf[2]);
            }
        }
    }

    // Epilogue: normalize, pack fp16 hi/lo to g_aoh/g_aol [m][512]
    float ia = 1.f / l_a, ib = 1.f / l_b;
    size_t mA = (size_t)b * SEQ + q0 + w * 16 + (lane >> 2);
    #pragma unroll
    for (int dt = 0; dt < 8; dt++) {
        int c  = dt * 8 + (lane & 3) * 2;
        int ci = h * 32 + (c >> 1);
        uint32_t hh, ll;
        hilo2h(o[dt][0] * ia, o[dt][1] * ia, hh, ll);
        g_aoh[mA * 512 + ci] = hh; g_aol[mA * 512 + ci] = ll;
        hilo2h(o[dt][2] * ib, o[dt][3] * ib, hh, ll);
        g_aoh[(mA + 8) * 512 + ci] = hh; g_aol[(mA + 8) * 512 + ci] = ll;
    }
}

// ---------------------------------------------------------------------------
extern "C" void kernel_launch(void* const* d_in, const int* in_sizes, int n_in,
                              void* d_out, int out_size)
{
    const float* x      = (const float*)d_in[0];
    const float* w_qkv  = (const float*)d_in[1];
    const float* w_proj = (const float*)d_in[2];
    const float* b_proj = (const float*)d_in[3];
    float* out = (float*)d_out;

    void *pxh, *pxl, *pwqh, *pwph, *pqh, *pql, *paoh, *paol;
    cudaGetSymbolAddress(&pxh, g_xh);   cudaGetSymbolAddress(&pxl, g_xl);
    cudaGetSymbolAddress(&pwqh, g_wqh); cudaGetSymbolAddress(&pwph, g_wph);
    cudaGetSymbolAddress(&pqh, g_qkvh); cudaGetSymbolAddress(&pql, g_qkvl);
    cudaGetSymbolAddress(&paoh, g_aoh); cudaGetSymbolAddress(&paol, g_aol);

    cudaFuncSetAttribute(mm2<0>, cudaFuncAttributeMaxDynamicSharedMemorySize, 147456);
    cudaFuncSetAttribute(mm2<1>, cudaFuncAttributeMaxDynamicSharedMemorySize, 147456);
    cudaFuncSetAttribute(flash2, cudaFuncAttributeMaxDynamicSharedMemorySize, 163840);

    // 1) Splits: x -> fp16 2-digit; weights -> fp16 1-digit
    split2h<<<4096, 256>>>(x,      (uint32_t*)pxh, (uint32_t*)pxl, 1048576);
    round1h<<<3072, 256>>>(w_qkv,  (uint32_t*)pwqh, 786432);
    round1h<<<1024, 256>>>(w_proj, (uint32_t*)pwph, 262144);

    // 2) QKV projection (fp16 2-term) -> bf16 hi/lo Q/K/V (Q scaled)
    mm2<0><<<dim3(24, 32), 512, 147456>>>(
        (uint32_t*)pxh, (uint32_t*)pxl, (uint32_t*)pwqh,
        nullptr, nullptr, (uint32_t*)pqh, (uint32_t*)pql, 3072, 1024);

    // 3) Attention (bf16 3-term, unchanged) -> fp16 hi/lo AO
    flash2<<<dim3(8, 32), 512, 163840>>>();

    // 4) Output projection (fp16 2-term) + bias
    mm2<1><<<dim3(8, 32), 512, 147456>>>(
        (uint32_t*)paoh, (uint32_t*)paol, (uint32_t*)pwph,
        b_proj, out, nullptr, nullptr, 1024, 1024);
}